// round 2
// baseline (speedup 1.0000x reference)
#include <cuda_runtime.h>
#include <stdint.h>

#define Nn    256
#define Cc    256
#define HWp   784
#define Dd    64
#define Pp    200
#define NCLSk 10
#define TPX   64
#define NTILES 13   // ceil(784/64)

// Precomputed per-replay by init kernel (deterministic).
__device__ float g_protoT[Dd * Pp];   // [k][p] transposed prototypes
__device__ float g_p2[Pp];            // ||proto_p||^2

// ---------------------------------------------------------------------------
// Init: transpose prototypes, compute ||p||^2, reset min-distance region to +inf
// ---------------------------------------------------------------------------
__global__ void init_kernel(const float* __restrict__ protos, float* __restrict__ out) {
    int t = blockIdx.x * blockDim.x + threadIdx.x;
    if (t < Dd * Pp) {
        int k = t / Pp, p = t % Pp;
        g_protoT[t] = protos[p * Dd + k];
    }
    if (t < Pp) {
        float s = 0.f;
        #pragma unroll 8
        for (int k = 0; k < Dd; k++) { float v = protos[t * Dd + k]; s += v * v; }
        g_p2[t] = s;
    }
    unsigned* md = (unsigned*)(out + Nn * NCLSk);
    for (int i = t; i < Nn * Pp; i += gridDim.x * blockDim.x)
        md[i] = 0x7F800000u;  // +inf
}

// ---------------------------------------------------------------------------
// Fused main kernel: GEMM1(relu) -> GEMM2(sigmoid) -> L2-dist GEMM3 -> spatial min
// One block = one (image, 64-pixel tile). 256 threads, 4x4 microtiles.
// ---------------------------------------------------------------------------
struct SmemT {
    float xs[64][64];       // x chunk   [k][px]        16.0 KB
    float ws[64][68];       // W1 chunk / W2 [d][k]     17.4 KB
    float hs[64][68];       // h then f  [d][px]        17.4 KB
    float pt[64][200];      // protoT    [k][p]         51.2 KB
    float x2s[64];          // per-pixel ||f||^2
    float p2s[Pp];
    unsigned pmin[Pp];
    float b1s[Dd];
    float b2s[Dd];
};

extern __shared__ char smem_raw[];

__global__ void __launch_bounds__(256, 2)
proto_main(const float* __restrict__ x,  const float* __restrict__ W1,
           const float* __restrict__ b1, const float* __restrict__ W2,
           const float* __restrict__ b2, float* __restrict__ out)
{
    SmemT& s = *reinterpret_cast<SmemT*>(smem_raw);
    const int tid  = threadIdx.x;
    const int n    = blockIdx.y;
    const int pix0 = blockIdx.x * TPX;
    const int tx = tid & 15, ty = tid >> 4;
    const int px0 = tx * 4, d0 = ty * 4;

    // Stage prototypes / constants / init smem mins
    for (int i = tid; i < Dd * Pp; i += 256) (&s.pt[0][0])[i] = g_protoT[i];
    for (int i = tid; i < Pp;      i += 256) { s.p2s[i] = g_p2[i]; s.pmin[i] = 0x7F800000u; }
    if (tid < Dd) { s.b1s[tid] = b1[tid]; s.b2s[tid] = b2[tid]; }

    const int r  = tid >> 2;          // 0..63 (staging row)
    const int c4 = (tid & 3) * 16;    // 0,16,32,48
    const float* xbase = x + (size_t)n * Cc * HWp;
    const bool full = (pix0 + TPX <= HWp);

    float acc[4][4];
    #pragma unroll
    for (int i = 0; i < 4; i++)
        #pragma unroll
        for (int j = 0; j < 4; j++) acc[i][j] = 0.f;

    // ---------------- GEMM1: h = relu(W1 @ x + b1), K = 256 in 4 chunks ---
    for (int kc = 0; kc < Cc; kc += 64) {
        // stage x chunk [64k][64px]
        if (full) {
            const float4* src = (const float4*)(xbase + (size_t)(kc + r) * HWp + pix0 + c4);
            float4* dst = (float4*)&s.xs[r][c4];
            #pragma unroll
            for (int j = 0; j < 4; j++) dst[j] = src[j];
        } else {
            #pragma unroll
            for (int j = 0; j < 16; j++) {
                int gp = pix0 + c4 + j; if (gp > HWp - 1) gp = HWp - 1;  // clamp: dup pixels are min-safe
                s.xs[r][c4 + j] = xbase[(size_t)(kc + r) * HWp + gp];
            }
        }
        // stage W1 chunk [64d][64k]
        {
            const float4* src = (const float4*)(W1 + r * Cc + kc + c4);
            float4* dst = (float4*)&s.ws[r][c4];
            #pragma unroll
            for (int j = 0; j < 4; j++) dst[j] = src[j];
        }
        __syncthreads();
        #pragma unroll 16
        for (int k = 0; k < 64; k++) {
            float4 b = *(const float4*)&s.xs[k][px0];
            float a0 = s.ws[d0+0][k], a1 = s.ws[d0+1][k], a2 = s.ws[d0+2][k], a3 = s.ws[d0+3][k];
            acc[0][0] += a0*b.x; acc[0][1] += a0*b.y; acc[0][2] += a0*b.z; acc[0][3] += a0*b.w;
            acc[1][0] += a1*b.x; acc[1][1] += a1*b.y; acc[1][2] += a1*b.z; acc[1][3] += a1*b.w;
            acc[2][0] += a2*b.x; acc[2][1] += a2*b.y; acc[2][2] += a2*b.z; acc[2][3] += a2*b.w;
            acc[3][0] += a3*b.x; acc[3][1] += a3*b.y; acc[3][2] += a3*b.z; acc[3][3] += a3*b.w;
        }
        __syncthreads();
    }
    // epilogue: bias + relu -> hs
    #pragma unroll
    for (int i = 0; i < 4; i++) {
        float bb = s.b1s[d0 + i];
        #pragma unroll
        for (int j = 0; j < 4; j++)
            s.hs[d0 + i][px0 + j] = fmaxf(acc[i][j] + bb, 0.f);
    }
    // stage W2 [64][64] into ws (safe: last sync already passed, ws dead, hs distinct)
    {
        const float4* src = (const float4*)(W2 + r * Dd + c4);
        float4* dst = (float4*)&s.ws[r][c4];
        #pragma unroll
        for (int j = 0; j < 4; j++) dst[j] = src[j];
    }
    __syncthreads();

    // ---------------- GEMM2: f = sigmoid(W2 @ h + b2), K = 64 --------------
    #pragma unroll
    for (int i = 0; i < 4; i++)
        #pragma unroll
        for (int j = 0; j < 4; j++) acc[i][j] = 0.f;
    #pragma unroll 16
    for (int k = 0; k < 64; k++) {
        float4 b = *(const float4*)&s.hs[k][px0];
        float a0 = s.ws[d0+0][k], a1 = s.ws[d0+1][k], a2 = s.ws[d0+2][k], a3 = s.ws[d0+3][k];
        acc[0][0] += a0*b.x; acc[0][1] += a0*b.y; acc[0][2] += a0*b.z; acc[0][3] += a0*b.w;
        acc[1][0] += a1*b.x; acc[1][1] += a1*b.y; acc[1][2] += a1*b.z; acc[1][3] += a1*b.w;
        acc[2][0] += a2*b.x; acc[2][1] += a2*b.y; acc[2][2] += a2*b.z; acc[2][3] += a2*b.w;
        acc[3][0] += a3*b.x; acc[3][1] += a3*b.y; acc[3][2] += a3*b.z; acc[3][3] += a3*b.w;
    }
    __syncthreads();   // all reads of hs (=h) done before overwriting with f
    #pragma unroll
    for (int i = 0; i < 4; i++) {
        float bb = s.b2s[d0 + i];
        #pragma unroll
        for (int j = 0; j < 4; j++) {
            float y = acc[i][j] + bb;
            s.hs[d0 + i][px0 + j] = 1.f / (1.f + __expf(-y));
        }
    }
    __syncthreads();

    // per-pixel ||f||^2
    if (tid < 64) {
        float ssum = 0.f;
        #pragma unroll 16
        for (int k = 0; k < 64; k++) { float v = s.hs[k][tid]; ssum += v * v; }
        s.x2s[tid] = ssum;
    }
    __syncthreads();

    // ---------------- GEMM3: dist = relu(||f||^2 - 2 f·p + ||p||^2), min --
    for (int pbase = 0; pbase < Pp; pbase += 64) {
        int p0 = pbase + d0;
        if (p0 < Pp) {
            #pragma unroll
            for (int i = 0; i < 4; i++)
                #pragma unroll
                for (int j = 0; j < 4; j++) acc[i][j] = 0.f;
            #pragma unroll 16
            for (int k = 0; k < 64; k++) {
                float4 a = *(const float4*)&s.pt[k][p0];
                float4 b = *(const float4*)&s.hs[k][px0];
                acc[0][0] += a.x*b.x; acc[0][1] += a.x*b.y; acc[0][2] += a.x*b.z; acc[0][3] += a.x*b.w;
                acc[1][0] += a.y*b.x; acc[1][1] += a.y*b.y; acc[1][2] += a.y*b.z; acc[1][3] += a.y*b.w;
                acc[2][0] += a.z*b.x; acc[2][1] += a.z*b.y; acc[2][2] += a.z*b.z; acc[2][3] += a.z*b.w;
                acc[3][0] += a.w*b.x; acc[3][1] += a.w*b.y; acc[3][2] += a.w*b.z; acc[3][3] += a.w*b.w;
            }
            #pragma unroll
            for (int i = 0; i < 4; i++) {
                int p = p0 + i;
                float pv = s.p2s[p];
                float m = 3.4e38f;
                #pragma unroll
                for (int j = 0; j < 4; j++) {
                    float d = s.x2s[px0 + j] - 2.f * acc[i][j] + pv;
                    d = fmaxf(d, 0.f);
                    m = fminf(m, d);
                }
                atomicMin(&s.pmin[p], __float_as_uint(m));  // valid: all values >= 0
            }
        }
    }
    __syncthreads();

    // combine tile mins into global min_distances (out + Nn*NCLS)
    unsigned* gmd = (unsigned*)(out + Nn * NCLSk) + (size_t)n * Pp;
    for (int p = tid; p < Pp; p += 256)
        atomicMin(&gmd[p], s.pmin[p]);
}

// ---------------------------------------------------------------------------
// Logits: logits[n,c] = sum_p (-min_d[n,p]) * lastW[c,p] + lastb[c]
// ---------------------------------------------------------------------------
__global__ void logits_kernel(const float* __restrict__ lastW,
                              const float* __restrict__ lastb,
                              float* __restrict__ out)
{
    __shared__ float lw[NCLSk * Pp];
    __shared__ float lb[NCLSk];
    int tid = threadIdx.x;
    for (int i = tid; i < NCLSk * Pp; i += blockDim.x) lw[i] = lastW[i];
    if (tid < NCLSk) lb[tid] = lastb[tid];
    __syncthreads();

    int n = blockIdx.x * blockDim.x + tid;
    if (n >= Nn) return;
    const float* md = out + Nn * NCLSk + (size_t)n * Pp;
    float accv[NCLSk];
    #pragma unroll
    for (int c = 0; c < NCLSk; c++) accv[c] = lb[c];
    for (int p = 0; p < Pp; p++) {
        float a = -md[p];
        #pragma unroll
        for (int c = 0; c < NCLSk; c++) accv[c] += a * lw[c * Pp + p];
    }
    #pragma unroll
    for (int c = 0; c < NCLSk; c++) out[n * NCLSk + c] = accv[c];
}

// ---------------------------------------------------------------------------
extern "C" void kernel_launch(void* const* d_in, const int* in_sizes, int n_in,
                              void* d_out, int out_size)
{
    const float* x      = (const float*)d_in[0];
    const float* W1     = (const float*)d_in[1];
    const float* b1     = (const float*)d_in[2];
    const float* W2     = (const float*)d_in[3];
    const float* b2     = (const float*)d_in[4];
    const float* protos = (const float*)d_in[5];
    const float* lastW  = (const float*)d_in[6];
    const float* lastb  = (const float*)d_in[7];
    float* out = (float*)d_out;

    cudaFuncSetAttribute(proto_main, cudaFuncAttributeMaxDynamicSharedMemorySize,
                         (int)sizeof(SmemT));

    init_kernel<<<(Nn * Pp + 255) / 256, 256>>>(protos, out);
    dim3 grid(NTILES, Nn);
    proto_main<<<grid, 256, sizeof(SmemT)>>>(x, W1, b1, W2, b2, out);
    logits_kernel<<<(Nn + 31) / 32, 32>>>(lastW, lastb, out);
}

// round 3
// speedup vs baseline: 1.3802x; 1.3802x over previous
#include <cuda_runtime.h>
#include <stdint.h>

#define Nn    256
#define Cc    256
#define HWp   784
#define Dd    64
#define Pp    200
#define PPAD  208
#define NCLSk 10
#define TPX   64          // pixels per tile
#define NTILES 13         // ceil(784/64)
#define COLS  128         // 2 images x 64 px
#define KC    16          // k-chunk for GEMM1

// Precomputed per replay (deterministic).
__device__ float g_W1T[Cc * Dd];        // [c][d]
__device__ float g_W2T[Dd * Dd];        // [k][d]
__device__ float g_protoT[Dd * PPAD];   // [k][p], zero-padded p>=200
__device__ float g_p2[PPAD];            // ||proto||^2 (0 for pad)

// ---------------- packed f32x2 helpers (ptxas won't auto-emit) -------------
#define FMA2(c, a, b) asm("fma.rn.f32x2 %0, %1, %2, %0;" : "+l"(c) : "l"(a), "l"(b))
#define DUP2(d, s)    asm("mov.b64 %0, {%1, %1};" : "=l"(d) : "r"(__float_as_uint(s)))
#define UNPK(lo, hi, v) asm("mov.b64 {%0, %1}, %2;" : "=f"(lo), "=f"(hi) : "l"(v))

__device__ __forceinline__ float fast_sigmoid(float x) {
    float t;
    asm("tanh.approx.f32 %0, %1;" : "=f"(t) : "f"(0.5f * x));
    return fmaf(0.5f, t, 0.5f);
}

// ---------------------------------------------------------------------------
__global__ void init_kernel(const float* __restrict__ W1, const float* __restrict__ W2,
                            const float* __restrict__ protos, float* __restrict__ out)
{
    int t0 = blockIdx.x * blockDim.x + threadIdx.x;
    int stride = gridDim.x * blockDim.x;
    for (int i = t0; i < Cc * Dd; i += stride) {           // W1T[c][d] = W1[d][c]
        int c = i / Dd, d = i % Dd;
        g_W1T[i] = W1[d * Cc + c];
    }
    for (int i = t0; i < Dd * Dd; i += stride) {           // W2T[k][d] = W2[d][k]
        int k = i / Dd, d = i % Dd;
        g_W2T[i] = W2[d * Dd + k];
    }
    for (int i = t0; i < Dd * PPAD; i += stride) {         // protoT[k][p]
        int k = i / PPAD, p = i % PPAD;
        g_protoT[i] = (p < Pp) ? protos[p * Dd + k] : 0.f;
    }
    for (int p = t0; p < PPAD; p += stride) {
        float s = 0.f;
        if (p < Pp) {
            #pragma unroll 8
            for (int k = 0; k < Dd; k++) { float v = protos[p * Dd + k]; s += v * v; }
        }
        g_p2[p] = s;
    }
    unsigned* md = (unsigned*)(out + Nn * NCLSk);
    for (int i = t0; i < Nn * Pp; i += stride) md[i] = 0x7F800000u;  // +inf
}

// ---------------------------------------------------------------------------
// Fused main: block = (64-px tile) x (2 images). 128 threads, 8x8 microtiles,
// packed fma.rn.f32x2 throughout.
// ---------------------------------------------------------------------------
struct SmemT {
    union {
        struct { float xs[KC][COLS]; float wsT[KC][Dd]; } g1;  // 8KB + 4KB
        float w2T[Dd][Dd];                                     // 16KB
        char pad_[16384];
    } u;
    float hs[Dd][COLS];       // h then f           32 KB
    float pt[Dd][PPAD];       // protoT             53.2 KB
    float p2s[PPAD];
    unsigned pmin[2][PPAD];
    float x2s[COLS];
    float b1s[Dd];
    float b2s[Dd];
};

extern __shared__ char smem_raw[];

__global__ void __launch_bounds__(128, 2)
proto_main(const float* __restrict__ x,
           const float* __restrict__ b1, const float* __restrict__ b2,
           float* __restrict__ out)
{
    SmemT& s = *reinterpret_cast<SmemT*>(smem_raw);
    const int tid  = threadIdx.x;
    const int pix0 = blockIdx.x * TPX;
    const int pair = blockIdx.y;             // image pair: images 2*pair, 2*pair+1
    const int tx = tid & 15, ty = tid >> 4;  // 16 x 8 threads
    const int col0 = tx * 8;                 // 8 columns per thread
    const int d0   = ty * 8;                 // 8 rows per thread
    const bool full = (pix0 + TPX <= HWp);

    // ---- stage prototypes / constants / smem-min init ----
    {
        const float4* src = (const float4*)g_protoT;
        float4* dst = (float4*)&s.pt[0][0];
        for (int i = tid; i < Dd * PPAD / 4; i += 128) dst[i] = src[i];
    }
    for (int i = tid; i < PPAD; i += 128) {
        s.p2s[i] = g_p2[i];
        s.pmin[0][i] = 0x7F800000u;
        s.pmin[1][i] = 0x7F800000u;
    }
    if (tid < Dd) { s.b1s[tid] = b1[tid]; s.b2s[tid] = b2[tid]; }

    unsigned long long acc[8][4];
    #pragma unroll
    for (int i = 0; i < 8; i++)
        #pragma unroll
        for (int j = 0; j < 4; j++) acc[i][j] = 0ull;

    // ================= GEMM1: h = relu(W1 @ x + b1), K=256 =================
    const int seg  = tid >> 4;   // 0..7  -> (k = seg>>1, img-half = seg&1)
    const int lane = tid & 15;
    for (int kc = 0; kc < Cc; kc += KC) {
        // stage x chunk [KC][COLS]
        #pragma unroll
        for (int j = 0; j < 4; j++) {
            int sg = seg + j * 8;
            int k = sg >> 1, half = sg & 1;
            int img = pair * 2 + half;
            const float* srow = x + (size_t)img * Cc * HWp + (size_t)(kc + k) * HWp;
            if (full) {
                *(float4*)&s.u.g1.xs[k][half * 64 + lane * 4] =
                    *(const float4*)(srow + pix0 + lane * 4);
            } else {
                #pragma unroll
                for (int e = 0; e < 4; e++) {
                    int gp = pix0 + lane * 4 + e; if (gp > HWp - 1) gp = HWp - 1;
                    s.u.g1.xs[k][half * 64 + lane * 4 + e] = srow[gp];
                }
            }
        }
        // stage W1T chunk [KC][64]
        {
            int kk = tid >> 3, dp = (tid & 7) * 8;
            const float4* src = (const float4*)(g_W1T + (size_t)(kc + kk) * Dd + dp);
            *(float4*)&s.u.g1.wsT[kk][dp]     = src[0];
            *(float4*)&s.u.g1.wsT[kk][dp + 4] = src[1];
        }
        __syncthreads();
        #pragma unroll
        for (int k = 0; k < KC; k++) {
            const float4 a0 = *(const float4*)&s.u.g1.wsT[k][d0];
            const float4 a1 = *(const float4*)&s.u.g1.wsT[k][d0 + 4];
            const ulonglong2 B0 = *(const ulonglong2*)&s.u.g1.xs[k][col0];
            const ulonglong2 B1 = *(const ulonglong2*)&s.u.g1.xs[k][col0 + 4];
            unsigned long long ad;
            DUP2(ad, a0.x); FMA2(acc[0][0], ad, B0.x); FMA2(acc[0][1], ad, B0.y); FMA2(acc[0][2], ad, B1.x); FMA2(acc[0][3], ad, B1.y);
            DUP2(ad, a0.y); FMA2(acc[1][0], ad, B0.x); FMA2(acc[1][1], ad, B0.y); FMA2(acc[1][2], ad, B1.x); FMA2(acc[1][3], ad, B1.y);
            DUP2(ad, a0.z); FMA2(acc[2][0], ad, B0.x); FMA2(acc[2][1], ad, B0.y); FMA2(acc[2][2], ad, B1.x); FMA2(acc[2][3], ad, B1.y);
            DUP2(ad, a0.w); FMA2(acc[3][0], ad, B0.x); FMA2(acc[3][1], ad, B0.y); FMA2(acc[3][2], ad, B1.x); FMA2(acc[3][3], ad, B1.y);
            DUP2(ad, a1.x); FMA2(acc[4][0], ad, B0.x); FMA2(acc[4][1], ad, B0.y); FMA2(acc[4][2], ad, B1.x); FMA2(acc[4][3], ad, B1.y);
            DUP2(ad, a1.y); FMA2(acc[5][0], ad, B0.x); FMA2(acc[5][1], ad, B0.y); FMA2(acc[5][2], ad, B1.x); FMA2(acc[5][3], ad, B1.y);
            DUP2(ad, a1.z); FMA2(acc[6][0], ad, B0.x); FMA2(acc[6][1], ad, B0.y); FMA2(acc[6][2], ad, B1.x); FMA2(acc[6][3], ad, B1.y);
            DUP2(ad, a1.w); FMA2(acc[7][0], ad, B0.x); FMA2(acc[7][1], ad, B0.y); FMA2(acc[7][2], ad, B1.x); FMA2(acc[7][3], ad, B1.y);
        }
        __syncthreads();
    }
    // epilogue: bias + relu -> hs
    #pragma unroll
    for (int i = 0; i < 8; i++) {
        float bb = s.b1s[d0 + i];
        float r[8];
        #pragma unroll
        for (int j = 0; j < 4; j++) UNPK(r[2 * j], r[2 * j + 1], acc[i][j]);
        float4 v0, v1;
        v0.x = fmaxf(r[0] + bb, 0.f); v0.y = fmaxf(r[1] + bb, 0.f);
        v0.z = fmaxf(r[2] + bb, 0.f); v0.w = fmaxf(r[3] + bb, 0.f);
        v1.x = fmaxf(r[4] + bb, 0.f); v1.y = fmaxf(r[5] + bb, 0.f);
        v1.z = fmaxf(r[6] + bb, 0.f); v1.w = fmaxf(r[7] + bb, 0.f);
        *(float4*)&s.hs[d0 + i][col0]     = v0;
        *(float4*)&s.hs[d0 + i][col0 + 4] = v1;
    }
    // stage W2T (overwrites union region; safe: last sync already drained macs)
    {
        int kk = tid >> 1, hp = (tid & 1) * 32;
        const float4* src = (const float4*)(g_W2T + (size_t)kk * Dd + hp);
        float4* dst = (float4*)&s.u.w2T[kk][hp];
        #pragma unroll
        for (int j = 0; j < 8; j++) dst[j] = src[j];
    }
    __syncthreads();

    // ================= GEMM2: f = sigmoid(W2 @ h + b2), K=64 ================
    #pragma unroll
    for (int i = 0; i < 8; i++)
        #pragma unroll
        for (int j = 0; j < 4; j++) acc[i][j] = 0ull;
    #pragma unroll 8
    for (int k = 0; k < Dd; k++) {
        const float4 a0 = *(const float4*)&s.u.w2T[k][d0];
        const float4 a1 = *(const float4*)&s.u.w2T[k][d0 + 4];
        const ulonglong2 B0 = *(const ulonglong2*)&s.hs[k][col0];
        const ulonglong2 B1 = *(const ulonglong2*)&s.hs[k][col0 + 4];
        unsigned long long ad;
        DUP2(ad, a0.x); FMA2(acc[0][0], ad, B0.x); FMA2(acc[0][1], ad, B0.y); FMA2(acc[0][2], ad, B1.x); FMA2(acc[0][3], ad, B1.y);
        DUP2(ad, a0.y); FMA2(acc[1][0], ad, B0.x); FMA2(acc[1][1], ad, B0.y); FMA2(acc[1][2], ad, B1.x); FMA2(acc[1][3], ad, B1.y);
        DUP2(ad, a0.z); FMA2(acc[2][0], ad, B0.x); FMA2(acc[2][1], ad, B0.y); FMA2(acc[2][2], ad, B1.x); FMA2(acc[2][3], ad, B1.y);
        DUP2(ad, a0.w); FMA2(acc[3][0], ad, B0.x); FMA2(acc[3][1], ad, B0.y); FMA2(acc[3][2], ad, B1.x); FMA2(acc[3][3], ad, B1.y);
        DUP2(ad, a1.x); FMA2(acc[4][0], ad, B0.x); FMA2(acc[4][1], ad, B0.y); FMA2(acc[4][2], ad, B1.x); FMA2(acc[4][3], ad, B1.y);
        DUP2(ad, a1.y); FMA2(acc[5][0], ad, B0.x); FMA2(acc[5][1], ad, B0.y); FMA2(acc[5][2], ad, B1.x); FMA2(acc[5][3], ad, B1.y);
        DUP2(ad, a1.z); FMA2(acc[6][0], ad, B0.x); FMA2(acc[6][1], ad, B0.y); FMA2(acc[6][2], ad, B1.x); FMA2(acc[6][3], ad, B1.y);
        DUP2(ad, a1.w); FMA2(acc[7][0], ad, B0.x); FMA2(acc[7][1], ad, B0.y); FMA2(acc[7][2], ad, B1.x); FMA2(acc[7][3], ad, B1.y);
    }
    __syncthreads();   // all reads of hs (=h) done before overwrite with f
    #pragma unroll
    for (int i = 0; i < 8; i++) {
        float bb = s.b2s[d0 + i];
        float r[8];
        #pragma unroll
        for (int j = 0; j < 4; j++) UNPK(r[2 * j], r[2 * j + 1], acc[i][j]);
        float4 v0, v1;
        v0.x = fast_sigmoid(r[0] + bb); v0.y = fast_sigmoid(r[1] + bb);
        v0.z = fast_sigmoid(r[2] + bb); v0.w = fast_sigmoid(r[3] + bb);
        v1.x = fast_sigmoid(r[4] + bb); v1.y = fast_sigmoid(r[5] + bb);
        v1.z = fast_sigmoid(r[6] + bb); v1.w = fast_sigmoid(r[7] + bb);
        *(float4*)&s.hs[d0 + i][col0]     = v0;
        *(float4*)&s.hs[d0 + i][col0 + 4] = v1;
    }
    __syncthreads();

    // per-column ||f||^2
    {
        float ssum = 0.f;
        #pragma unroll 16
        for (int k = 0; k < Dd; k++) { float v = s.hs[k][tid]; ssum = fmaf(v, v, ssum); }
        s.x2s[tid] = ssum;
    }
    __syncthreads();

    // ============ GEMM3: dist = relu(x2 - 2 f.p + p2); spatial min ==========
    const int img = tx >> 3;  // this thread's 8 columns live in one image
    float myx2[8];
    #pragma unroll
    for (int j = 0; j < 8; j++) myx2[j] = s.x2s[col0 + j];

    for (int pc = 0; pc < 4; pc++) {
        int p0 = pc * 64 + d0;
        if (p0 >= Pp) continue;   // tail chunk: only ty==0 active (p 192..199)
        #pragma unroll
        for (int i = 0; i < 8; i++)
            #pragma unroll
            for (int j = 0; j < 4; j++) acc[i][j] = 0ull;
        #pragma unroll 8
        for (int k = 0; k < Dd; k++) {
            const float4 a0 = *(const float4*)&s.pt[k][p0];
            const float4 a1 = *(const float4*)&s.pt[k][p0 + 4];
            const ulonglong2 B0 = *(const ulonglong2*)&s.hs[k][col0];
            const ulonglong2 B1 = *(const ulonglong2*)&s.hs[k][col0 + 4];
            unsigned long long ad;
            DUP2(ad, a0.x); FMA2(acc[0][0], ad, B0.x); FMA2(acc[0][1], ad, B0.y); FMA2(acc[0][2], ad, B1.x); FMA2(acc[0][3], ad, B1.y);
            DUP2(ad, a0.y); FMA2(acc[1][0], ad, B0.x); FMA2(acc[1][1], ad, B0.y); FMA2(acc[1][2], ad, B1.x); FMA2(acc[1][3], ad, B1.y);
            DUP2(ad, a0.z); FMA2(acc[2][0], ad, B0.x); FMA2(acc[2][1], ad, B0.y); FMA2(acc[2][2], ad, B1.x); FMA2(acc[2][3], ad, B1.y);
            DUP2(ad, a0.w); FMA2(acc[3][0], ad, B0.x); FMA2(acc[3][1], ad, B0.y); FMA2(acc[3][2], ad, B1.x); FMA2(acc[3][3], ad, B1.y);
            DUP2(ad, a1.x); FMA2(acc[4][0], ad, B0.x); FMA2(acc[4][1], ad, B0.y); FMA2(acc[4][2], ad, B1.x); FMA2(acc[4][3], ad, B1.y);
            DUP2(ad, a1.y); FMA2(acc[5][0], ad, B0.x); FMA2(acc[5][1], ad, B0.y); FMA2(acc[5][2], ad, B1.x); FMA2(acc[5][3], ad, B1.y);
            DUP2(ad, a1.z); FMA2(acc[6][0], ad, B0.x); FMA2(acc[6][1], ad, B0.y); FMA2(acc[6][2], ad, B1.x); FMA2(acc[6][3], ad, B1.y);
            DUP2(ad, a1.w); FMA2(acc[7][0], ad, B0.x); FMA2(acc[7][1], ad, B0.y); FMA2(acc[7][2], ad, B1.x); FMA2(acc[7][3], ad, B1.y);
        }
        #pragma unroll
        for (int i = 0; i < 8; i++) {
            int p = p0 + i;
            float pv = s.p2s[p];
            float m = 3.4e38f;
            #pragma unroll
            for (int j = 0; j < 4; j++) {
                float v0, v1;
                UNPK(v0, v1, acc[i][j]);
                float dA = fmaxf(fmaf(-2.f, v0, myx2[2 * j]     + pv), 0.f);
                float dB = fmaxf(fmaf(-2.f, v1, myx2[2 * j + 1] + pv), 0.f);
                m = fminf(m, fminf(dA, dB));
            }
            atomicMin(&s.pmin[img][p], __float_as_uint(m));  // valid: all >= 0
        }
    }
    __syncthreads();

    // flush tile mins to global min_distances
    unsigned* gmd = (unsigned*)(out + Nn * NCLSk);
    #pragma unroll
    for (int im = 0; im < 2; im++) {
        int n = pair * 2 + im;
        for (int p = tid; p < Pp; p += 128)
            atomicMin(&gmd[(size_t)n * Pp + p], s.pmin[im][p]);
    }
}

// ---------------------------------------------------------------------------
__global__ void logits_kernel(const float* __restrict__ lastW,
                              const float* __restrict__ lastb,
                              float* __restrict__ out)
{
    __shared__ float lw[NCLSk * Pp];
    __shared__ float lb[NCLSk];
    int tid = threadIdx.x;
    for (int i = tid; i < NCLSk * Pp; i += blockDim.x) lw[i] = lastW[i];
    if (tid < NCLSk) lb[tid] = lastb[tid];
    __syncthreads();

    int n = blockIdx.x * blockDim.x + tid;
    if (n >= Nn) return;
    const float* md = out + Nn * NCLSk + (size_t)n * Pp;
    float accv[NCLSk];
    #pragma unroll
    for (int c = 0; c < NCLSk; c++) accv[c] = lb[c];
    for (int p = 0; p < Pp; p++) {
        float a = -md[p];
        #pragma unroll
        for (int c = 0; c < NCLSk; c++) accv[c] = fmaf(a, lw[c * Pp + p], accv[c]);
    }
    #pragma unroll
    for (int c = 0; c < NCLSk; c++) out[n * NCLSk + c] = accv[c];
}

// ---------------------------------------------------------------------------
extern "C" void kernel_launch(void* const* d_in, const int* in_sizes, int n_in,
                              void* d_out, int out_size)
{
    const float* x      = (const float*)d_in[0];
    const float* W1     = (const float*)d_in[1];
    const float* b1     = (const float*)d_in[2];
    const float* W2     = (const float*)d_in[3];
    const float* b2     = (const float*)d_in[4];
    const float* protos = (const float*)d_in[5];
    const float* lastW  = (const float*)d_in[6];
    const float* lastb  = (const float*)d_in[7];
    float* out = (float*)d_out;

    cudaFuncSetAttribute(proto_main, cudaFuncAttributeMaxDynamicSharedMemorySize,
                         (int)sizeof(SmemT));

    init_kernel<<<128, 256>>>(W1, W2, protos, out);
    dim3 grid(NTILES, Nn / 2);
    proto_main<<<grid, 128, sizeof(SmemT)>>>(x, b1, b2, out);
    logits_kernel<<<(Nn + 31) / 32, 32>>>(lastW, lastb, out);
}

// round 5
// speedup vs baseline: 1.9554x; 1.4168x over previous
#include <cuda_runtime.h>
#include <cuda_bf16.h>
#include <stdint.h>

#define Nn    256
#define Cc    256
#define HWp   784
#define Dd    64
#define Pp    200
#define PPAD  256
#define NCLSk 10
#define TPX   128
#define NTILES 7     // ceil(784/128)
#define LDA   72     // padded row stride in bf16 elems (144 B = 9*16B, conflict-free)
#define ROWB  144    // row stride bytes

// ---------------- pre-split weights/prototypes (filled per replay) ---------
__device__ __align__(16) __nv_bfloat16 g_W1h[Dd * Cc], g_W1l[Dd * Cc];
__device__ __align__(16) __nv_bfloat16 g_W2h[Dd * Dd], g_W2l[Dd * Dd];
__device__ __align__(16) __nv_bfloat16 g_Ph[PPAD * Dd], g_Pl[PPAD * Dd];
__device__ float g_p2[PPAD];

// ---------------- helpers --------------------------------------------------
__device__ __forceinline__ uint32_t smem_u32(const void* p) {
    uint32_t a;
    asm("{ .reg .u64 t; cvta.to.shared.u64 t, %1; cvt.u32.u64 %0, t; }" : "=r"(a) : "l"(p));
    return a;
}
__device__ __forceinline__ void ldsm4(uint32_t* r, uint32_t addr) {
    asm volatile("ldmatrix.sync.aligned.m8n8.x4.shared.b16 {%0,%1,%2,%3}, [%4];"
                 : "=r"(r[0]), "=r"(r[1]), "=r"(r[2]), "=r"(r[3]) : "r"(addr));
}
__device__ __forceinline__ void mma_bf16(float* d, const uint32_t* a, const uint32_t* b) {
    asm volatile("mma.sync.aligned.m16n8k16.row.col.f32.bf16.bf16.f32 "
                 "{%0,%1,%2,%3}, {%4,%5,%6,%7}, {%8,%9}, {%0,%1,%2,%3};"
                 : "+f"(d[0]), "+f"(d[1]), "+f"(d[2]), "+f"(d[3])
                 : "r"(a[0]), "r"(a[1]), "r"(a[2]), "r"(a[3]), "r"(b[0]), "r"(b[1]));
}
__device__ __forceinline__ uint32_t split_pack(float a, float b, uint32_t& lo) {
    __nv_bfloat16 ha = __float2bfloat16(a), hb = __float2bfloat16(b);
    float ra = a - __bfloat162float(ha), rb = b - __bfloat162float(hb);
    __nv_bfloat16 la = __float2bfloat16(ra), lb = __float2bfloat16(rb);
    lo = (uint32_t)__bfloat16_as_ushort(la) | ((uint32_t)__bfloat16_as_ushort(lb) << 16);
    return (uint32_t)__bfloat16_as_ushort(ha) | ((uint32_t)__bfloat16_as_ushort(hb) << 16);
}
__device__ __forceinline__ float fast_sigmoid(float x) {
    float t;
    asm("tanh.approx.f32 %0, %1;" : "=f"(t) : "f"(0.5f * x));
    return fmaf(0.5f, t, 0.5f);
}

// ---------------------------------------------------------------------------
__global__ void init_kernel(const float* __restrict__ W1, const float* __restrict__ W2,
                            const float* __restrict__ protos, float* __restrict__ out)
{
    int t0 = blockIdx.x * blockDim.x + threadIdx.x;
    int stride = gridDim.x * blockDim.x;
    for (int i = t0; i < Dd * Cc; i += stride) {
        uint32_t lo; uint32_t hi = split_pack(W1[i], 0.f, lo);
        g_W1h[i] = __ushort_as_bfloat16((unsigned short)hi);
        g_W1l[i] = __ushort_as_bfloat16((unsigned short)lo);
    }
    for (int i = t0; i < Dd * Dd; i += stride) {
        uint32_t lo; uint32_t hi = split_pack(W2[i], 0.f, lo);
        g_W2h[i] = __ushort_as_bfloat16((unsigned short)hi);
        g_W2l[i] = __ushort_as_bfloat16((unsigned short)lo);
    }
    for (int i = t0; i < PPAD * Dd; i += stride) {
        int p = i / Dd;
        float v = (p < Pp) ? protos[i] : 0.f;
        uint32_t lo; uint32_t hi = split_pack(v, 0.f, lo);
        g_Ph[i] = __ushort_as_bfloat16((unsigned short)hi);
        g_Pl[i] = __ushort_as_bfloat16((unsigned short)lo);
    }
    for (int p = t0; p < PPAD; p += stride) {
        float s = 0.f;
        if (p < Pp) {
            #pragma unroll 8
            for (int k = 0; k < Dd; k++) { float v = protos[p * Dd + k]; s += v * v; }
        }
        g_p2[p] = s;
    }
    unsigned* md = (unsigned*)(out + Nn * NCLSk);
    for (int i = t0; i < Nn * Pp; i += stride) md[i] = 0x7F800000u;  // +inf
}

// ---------------------------------------------------------------------------
// Smem offsets (row bases all 16B aligned; ROWB=144=9*16)
#define OFF_B1  0
#define OFF_B2  256
#define OFF_X2  512
#define OFF_P2  1024
#define OFF_PM  2048
#define OFF_XH  3072                    // 128*144 = 18432
#define OFF_XL  (OFF_XH + 18432)
#define OFF_WH  (OFF_XL + 18432)        // 64*144 = 9216
#define OFF_WL  (OFF_WH + 9216)
#define OFF_HH  (OFF_WL + 9216)
#define OFF_HL  (OFF_HH + 18432)
#define SMEM_TOT (OFF_HL + 18432)       // 95232 B -> 2 CTAs/SM

extern __shared__ char smem[];

__global__ void __launch_bounds__(128)
proto_main(const float* __restrict__ x,
           const float* __restrict__ b1, const float* __restrict__ b2,
           float* __restrict__ out)
{
    const uint32_t sb = smem_u32(smem);
    const int tid = threadIdx.x;
    const int l   = tid & 31;
    const int R   = (tid >> 5) * 32;            // warp's pixel-row base
    const int img = blockIdx.y;
    const int pix0 = blockIdx.x * TPX;

    float* b1s = (float*)(smem + OFF_B1);
    float* b2s = (float*)(smem + OFF_B2);
    float* x2s = (float*)(smem + OFF_X2);
    float* p2s = (float*)(smem + OFF_P2);
    unsigned* pmin = (unsigned*)(smem + OFF_PM);

    if (tid < Dd) { b1s[tid] = b1[tid]; b2s[tid] = b2[tid]; }
    for (int i = tid; i < PPAD; i += 128) { p2s[i] = g_p2[i]; pmin[i] = 0x7F800000u; }

    // per-lane ldmatrix offsets (bytes, within a tile at given row-base)
    const uint32_t aoff = (uint32_t)(l & 15) * ROWB + ((l >> 4) << 4);
    const uint32_t boff = (uint32_t)((l & 7) + ((l >> 4) << 3)) * ROWB + (((l >> 3) & 1) << 4);
    const uint32_t aBaseH = sb + OFF_XH + R * ROWB + aoff;
    const uint32_t aBaseL = sb + OFF_XL + R * ROWB + aoff;
    const uint32_t hBaseH = sb + OFF_HH + R * ROWB + aoff;
    const uint32_t hBaseL = sb + OFF_HL + R * ROWB + aoff;
    const uint32_t bBaseH = sb + OFF_WH + boff;
    const uint32_t bBaseL = sb + OFF_WL + boff;

    int mypx = pix0 + tid;
    int gpx = mypx < HWp ? mypx : HWp - 1;      // clamp: duplicates are min-safe
    const float* xim = x + (size_t)img * Cc * HWp;
    const uint32_t myrow = (uint32_t)tid * ROWB;

    float acc[2][8][4];

    // ================= GEMM1: h[px][d] = relu(X · W1^T + b1), K=256 ========
    #pragma unroll
    for (int mt = 0; mt < 2; mt++)
        #pragma unroll
        for (int nt = 0; nt < 8; nt++)
            #pragma unroll
            for (int e = 0; e < 4; e++) acc[mt][nt][e] = 0.f;

    for (int kc = 0; kc < 4; kc++) {
        // stage X chunk: thread = pixel row, 64 channels -> hi/lo
        #pragma unroll
        for (int grp = 0; grp < 8; grp++) {
            float v[8];
            #pragma unroll
            for (int e = 0; e < 8; e++)
                v[e] = __ldg(xim + (size_t)(kc * 64 + grp * 8 + e) * HWp + gpx);
            uint4 hq, lq;
            hq.x = split_pack(v[0], v[1], lq.x);
            hq.y = split_pack(v[2], v[3], lq.y);
            hq.z = split_pack(v[4], v[5], lq.z);
            hq.w = split_pack(v[6], v[7], lq.w);
            *(uint4*)(smem + OFF_XH + myrow + grp * 16) = hq;
            *(uint4*)(smem + OFF_XL + myrow + grp * 16) = lq;
        }
        // stage W1 chunk [64 d][64 c]: tid<64 hi plane, tid>=64 lo plane
        {
            int d = tid & 63;
            const uint4* src = (const uint4*)((tid < 64 ? g_W1h : g_W1l) + d * Cc + kc * 64);
            char* dst = smem + (tid < 64 ? OFF_WH : OFF_WL) + d * ROWB;
            #pragma unroll
            for (int j = 0; j < 8; j++) *(uint4*)(dst + j * 16) = src[j];
        }
        __syncthreads();
        #pragma unroll
        for (int ks = 0; ks < 4; ks++) {
            const uint32_t kk2 = ks * 32;
            uint32_t ah[2][4], al[2][4], bh[4][4], bl[4][4];
            #pragma unroll
            for (int mt = 0; mt < 2; mt++) {
                ldsm4(ah[mt], aBaseH + mt * (16 * ROWB) + kk2);
                ldsm4(al[mt], aBaseL + mt * (16 * ROWB) + kk2);
            }
            #pragma unroll
            for (int np = 0; np < 4; np++) {
                ldsm4(bh[np], bBaseH + np * (16 * ROWB) + kk2);
                ldsm4(bl[np], bBaseL + np * (16 * ROWB) + kk2);
            }
            #pragma unroll
            for (int mt = 0; mt < 2; mt++)
                #pragma unroll
                for (int nt = 0; nt < 8; nt++) {
                    mma_bf16(acc[mt][nt], ah[mt], &bh[nt >> 1][(nt & 1) * 2]);
                    mma_bf16(acc[mt][nt], al[mt], &bh[nt >> 1][(nt & 1) * 2]);
                    mma_bf16(acc[mt][nt], ah[mt], &bl[nt >> 1][(nt & 1) * 2]);
                }
        }
        __syncthreads();
    }
    // epilogue 1: bias+relu -> HS planes
    {
        const int rq = l >> 2, cq = (l & 3) * 2;
        #pragma unroll
        for (int mt = 0; mt < 2; mt++)
            #pragma unroll
            for (int nt = 0; nt < 8; nt++) {
                int col = nt * 8 + cq;
                float bb0 = b1s[col], bb1 = b1s[col + 1];
                int r0 = R + mt * 16 + rq, r1 = r0 + 8;
                uint32_t lo, hi;
                hi = split_pack(fmaxf(acc[mt][nt][0] + bb0, 0.f),
                                fmaxf(acc[mt][nt][1] + bb1, 0.f), lo);
                *(uint32_t*)(smem + OFF_HH + r0 * ROWB + col * 2) = hi;
                *(uint32_t*)(smem + OFF_HL + r0 * ROWB + col * 2) = lo;
                hi = split_pack(fmaxf(acc[mt][nt][2] + bb0, 0.f),
                                fmaxf(acc[mt][nt][3] + bb1, 0.f), lo);
                *(uint32_t*)(smem + OFF_HH + r1 * ROWB + col * 2) = hi;
                *(uint32_t*)(smem + OFF_HL + r1 * ROWB + col * 2) = lo;
            }
    }
    // stage W2 into W region (all warps past GEMM1 ldmatrix via last sync)
    {
        int d = tid & 63;
        const uint4* src = (const uint4*)((tid < 64 ? g_W2h : g_W2l) + d * Dd);
        char* dst = smem + (tid < 64 ? OFF_WH : OFF_WL) + d * ROWB;
        #pragma unroll
        for (int j = 0; j < 8; j++) *(uint4*)(dst + j * 16) = src[j];
    }
    __syncthreads();

    // ================= GEMM2: f = sigmoid(h · W2^T + b2), K=64 =============
    #pragma unroll
    for (int mt = 0; mt < 2; mt++)
        #pragma unroll
        for (int nt = 0; nt < 8; nt++)
            #pragma unroll
            for (int e = 0; e < 4; e++) acc[mt][nt][e] = 0.f;
    #pragma unroll
    for (int ks = 0; ks < 4; ks++) {
        const uint32_t kk2 = ks * 32;
        uint32_t ah[2][4], al[2][4], bh[4][4], bl[4][4];
        #pragma unroll
        for (int mt = 0; mt < 2; mt++) {
            ldsm4(ah[mt], hBaseH + mt * (16 * ROWB) + kk2);
            ldsm4(al[mt], hBaseL + mt * (16 * ROWB) + kk2);
        }
        #pragma unroll
        for (int np = 0; np < 4; np++) {
            ldsm4(bh[np], bBaseH + np * (16 * ROWB) + kk2);
            ldsm4(bl[np], bBaseL + np * (16 * ROWB) + kk2);
        }
        #pragma unroll
        for (int mt = 0; mt < 2; mt++)
            #pragma unroll
            for (int nt = 0; nt < 8; nt++) {
                mma_bf16(acc[mt][nt], ah[mt], &bh[nt >> 1][(nt & 1) * 2]);
                mma_bf16(acc[mt][nt], al[mt], &bh[nt >> 1][(nt & 1) * 2]);
                mma_bf16(acc[mt][nt], ah[mt], &bl[nt >> 1][(nt & 1) * 2]);
            }
    }
    // epilogue 2: sigmoid -> f into XA planes; per-row ||f||^2
    {
        const int rq = l >> 2, cq = (l & 3) * 2;
        float ps[4] = {0.f, 0.f, 0.f, 0.f};
        #pragma unroll
        for (int mt = 0; mt < 2; mt++)
            #pragma unroll
            for (int nt = 0; nt < 8; nt++) {
                int col = nt * 8 + cq;
                float bb0 = b2s[col], bb1 = b2s[col + 1];
                int r0 = R + mt * 16 + rq, r1 = r0 + 8;
                float f0 = fast_sigmoid(acc[mt][nt][0] + bb0);
                float f1 = fast_sigmoid(acc[mt][nt][1] + bb1);
                float f2 = fast_sigmoid(acc[mt][nt][2] + bb0);
                float f3 = fast_sigmoid(acc[mt][nt][3] + bb1);
                ps[mt * 2 + 0] = fmaf(f0, f0, fmaf(f1, f1, ps[mt * 2 + 0]));
                ps[mt * 2 + 1] = fmaf(f2, f2, fmaf(f3, f3, ps[mt * 2 + 1]));
                uint32_t lo, hi;
                hi = split_pack(f0, f1, lo);
                *(uint32_t*)(smem + OFF_XH + r0 * ROWB + col * 2) = hi;
                *(uint32_t*)(smem + OFF_XL + r0 * ROWB + col * 2) = lo;
                hi = split_pack(f2, f3, lo);
                *(uint32_t*)(smem + OFF_XH + r1 * ROWB + col * 2) = hi;
                *(uint32_t*)(smem + OFF_XL + r1 * ROWB + col * 2) = lo;
            }
        #pragma unroll
        for (int s = 0; s < 4; s++) {
            ps[s] += __shfl_xor_sync(0xFFFFFFFFu, ps[s], 1);
            ps[s] += __shfl_xor_sync(0xFFFFFFFFu, ps[s], 2);
        }
        if ((l & 3) == 0) {
            x2s[R + rq]      = ps[0];
            x2s[R + rq + 8]  = ps[1];
            x2s[R + 16 + rq] = ps[2];
            x2s[R + 24 + rq] = ps[3];
        }
    }
    __syncthreads();

    // ===== GEMM3: dist[px][p] = relu(x2 - 2 f·p + p2); min over px =========
    const int rq = l >> 2, cq = (l & 3) * 2;
    float rx2[4] = { x2s[R + rq], x2s[R + rq + 8], x2s[R + 16 + rq], x2s[R + 24 + rq] };

    for (int pb = 0; pb < 4; pb++) {
        // stage proto block [64 p][64 k]
        {
            int d = tid & 63;
            const uint4* src = (const uint4*)((tid < 64 ? g_Ph : g_Pl) + (pb * 64 + d) * Dd);
            char* dst = smem + (tid < 64 ? OFF_WH : OFF_WL) + d * ROWB;
            #pragma unroll
            for (int j = 0; j < 8; j++) *(uint4*)(dst + j * 16) = src[j];
        }
        __syncthreads();
        #pragma unroll
        for (int mt = 0; mt < 2; mt++)
            #pragma unroll
            for (int nt = 0; nt < 8; nt++)
                #pragma unroll
                for (int e = 0; e < 4; e++) acc[mt][nt][e] = 0.f;
        #pragma unroll
        for (int ks = 0; ks < 4; ks++) {
            const uint32_t kk2 = ks * 32;
            uint32_t ah[2][4], al[2][4], bh[4][4], bl[4][4];
            #pragma unroll
            for (int mt = 0; mt < 2; mt++) {
                ldsm4(ah[mt], aBaseH + mt * (16 * ROWB) + kk2);
                ldsm4(al[mt], aBaseL + mt * (16 * ROWB) + kk2);
            }
            #pragma unroll
            for (int np = 0; np < 4; np++) {
                ldsm4(bh[np], bBaseH + np * (16 * ROWB) + kk2);
                ldsm4(bl[np], bBaseL + np * (16 * ROWB) + kk2);
            }
            #pragma unroll
            for (int mt = 0; mt < 2; mt++)
                #pragma unroll
                for (int nt = 0; nt < 8; nt++) {
                    mma_bf16(acc[mt][nt], ah[mt], &bh[nt >> 1][(nt & 1) * 2]);
                    mma_bf16(acc[mt][nt], al[mt], &bh[nt >> 1][(nt & 1) * 2]);
                    mma_bf16(acc[mt][nt], ah[mt], &bl[nt >> 1][(nt & 1) * 2]);
                }
        }
        // epilogue: distances + min over rows (regs -> shfl -> smem atomic)
        #pragma unroll
        for (int nt = 0; nt < 8; nt++) {
            int colA = pb * 64 + nt * 8 + cq;
            float p2a = p2s[colA], p2b = p2s[colA + 1];
            float mA = 3.4e38f, mB = 3.4e38f;
            #pragma unroll
            for (int mt = 0; mt < 2; mt++) {
                float d0 = fmaxf(fmaf(-2.f, acc[mt][nt][0], rx2[mt * 2 + 0] + p2a), 0.f);
                float d1 = fmaxf(fmaf(-2.f, acc[mt][nt][1], rx2[mt * 2 + 0] + p2b), 0.f);
                float d2 = fmaxf(fmaf(-2.f, acc[mt][nt][2], rx2[mt * 2 + 1] + p2a), 0.f);
                float d3 = fmaxf(fmaf(-2.f, acc[mt][nt][3], rx2[mt * 2 + 1] + p2b), 0.f);
                mA = fminf(mA, fminf(d0, d2));
                mB = fminf(mB, fminf(d1, d3));
            }
            #pragma unroll
            for (int off = 4; off < 32; off <<= 1) {
                mA = fminf(mA, __shfl_xor_sync(0xFFFFFFFFu, mA, off));
                mB = fminf(mB, __shfl_xor_sync(0xFFFFFFFFu, mB, off));
            }
            if (l < 4) {
                atomicMin(&pmin[colA],     __float_as_uint(mA));
                atomicMin(&pmin[colA + 1], __float_as_uint(mB));
            }
        }
        __syncthreads();
    }

    // flush tile mins to global
    unsigned* gmd = (unsigned*)(out + Nn * NCLSk) + (size_t)img * Pp;
    for (int p = tid; p < Pp; p += 128)
        atomicMin(&gmd[p], pmin[p]);
}

// ---------------------------------------------------------------------------
__global__ void logits_kernel(const float* __restrict__ lastW,
                              const float* __restrict__ lastb,
                              float* __restrict__ out)
{
    __shared__ float lw[NCLSk * Pp];
    __shared__ float lb[NCLSk];
    int tid = threadIdx.x;
    for (int i = tid; i < NCLSk * Pp; i += blockDim.x) lw[i] = lastW[i];
    if (tid < NCLSk) lb[tid] = lastb[tid];
    __syncthreads();

    int n = blockIdx.x * blockDim.x + tid;
    if (n >= Nn) return;
    const float* md = out + Nn * NCLSk + (size_t)n * Pp;
    float accv[NCLSk];
    #pragma unroll
    for (int c = 0; c < NCLSk; c++) accv[c] = lb[c];
    for (int p = 0; p < Pp; p++) {
        float a = -md[p];
        #pragma unroll
        for (int c = 0; c < NCLSk; c++) accv[c] = fmaf(a, lw[c * Pp + p], accv[c]);
    }
    #pragma unroll
    for (int c = 0; c < NCLSk; c++) out[n * NCLSk + c] = accv[c];
}

// ---------------------------------------------------------------------------
extern "C" void kernel_launch(void* const* d_in, const int* in_sizes, int n_in,
                              void* d_out, int out_size)
{
    const float* x      = (const float*)d_in[0];
    const float* W1     = (const float*)d_in[1];
    const float* b1     = (const float*)d_in[2];
    const float* W2     = (const float*)d_in[3];
    const float* b2     = (const float*)d_in[4];
    const float* protos = (const float*)d_in[5];
    const float* lastW  = (const float*)d_in[6];
    const float* lastb  = (const float*)d_in[7];
    float* out = (float*)d_out;

    cudaFuncSetAttribute(proto_main, cudaFuncAttributeMaxDynamicSharedMemorySize, SMEM_TOT);

    init_kernel<<<128, 256>>>(W1, W2, protos, out);
    dim3 grid(NTILES, Nn);
    proto_main<<<grid, 128, SMEM_TOT>>>(x, b1, b2, out);
    logits_kernel<<<(Nn + 31) / 32, 32>>>(lastW, lastb, out);
}